// round 1
// baseline (speedup 1.0000x reference)
#include <cuda_runtime.h>
#include <cuda_bf16.h>
#include <math.h>

#define T_  64
#define N_  32
#define C_  128
#define D_  64

// Scratch (no allocation allowed in kernel_launch)
__device__ float g_fs[T_ * N_ * C_];     // fs[t][n][c]
__device__ float g_fssum[T_ * N_];       // sum over c

// ---------------------------------------------------------------------------
// K1: one warp per (n,c) chain. Lane L owns Jeffress units j=L and j=L+32.
// Covers: Jeffress LIF -> kint dot -> integrator IF -> square model -> fs.
// ---------------------------------------------------------------------------
__global__ __launch_bounds__(128) void k1_chains(
    const float* __restrict__ x,
    const float* __restrict__ w1, const float* __restrict__ b1,
    const float* __restrict__ w2, const float* __restrict__ b2)
{
    __shared__ float xs0[4][128];   // x0 padded: xs0[w][63+t] = x0[t], [0..62]=0
    __shared__ float xs1[4][128];   // x1 padded likewise

    const int tid  = threadIdx.x;
    const int warp = tid >> 5;
    const int lane = tid & 31;
    const int chain  = blockIdx.x * 4 + warp;
    const int n      = chain >> 7;          // chain / C_
    const int c      = chain & 127;
    const int c_base = (blockIdx.x * 4) & 127;   // block spans 4 consecutive c, same n

    // Zero the pad entries: [0..62] and [127] of each array
    for (int e = tid; e < 2 * 4 * 64; e += 128) {
        int arr = e >> 8;
        int w   = (e >> 6) & 3;
        int p   = e & 63;
        int pos = (p < 63) ? p : 127;
        if (arr == 0) xs0[w][pos] = 0.f; else xs1[w][pos] = 0.f;
    }
    // Fill: xs{0,1}[w][63+t] = x[t][n][i][c_base+w]
    for (int e = tid; e < 2 * 4 * 64; e += 128) {
        int t = e >> 3;
        int i = (e >> 2) & 1;
        int w = e & 3;
        float v = x[((t * N_ + n) * 2 + i) * C_ + c_base + w];
        if (i == 0) xs0[w][63 + t] = v; else xs1[w][63 + t] = v;
    }
    __syncthreads();

    // kint for this lane's two units, computed in double (robust to fast-math;
    // kint(|d|=32) = 1.0000001 sits 1 ulp above the integrator threshold).
    const int ad0 = 32 - lane;                       // j=lane    -> |d| in [1,32]
    const int ad1 = (lane == 0) ? 1 : lane;          // j=lane+32 -> |d|, d==0 clamped to 1
    const float k0 = (float)(1.0 / (1.0 - exp(-(double)ad0 * 0.5)));
    const float k1 = (float)(1.0 / (1.0 - exp(-(double)ad1 * 0.5)));

    // square-model params: lanes 0..9 active, others carry zeros (branchless)
    const float w1k = (lane < 10) ? w1[lane] : 0.f;
    const float b1k = (lane < 10) ? b1[lane] : 0.f;
    const float w2k = (lane < 10) ? w2[lane] : 0.f;
    const float b2v = b2[0];

    const float* __restrict__ px0 = xs0[warp];
    const float* __restrict__ px1 = xs1[warp];

    float vj0 = 0.f, vj1 = 0.f;   // Jeffress LIF membranes (2 per lane)
    float vi = 0.f;               // integrator IF (replicated across lanes)
    float f1 = 0.f;               // filter 1 (replicated)
    float v1 = 0.f, f2 = 0.f;     // per-lane (lanes 0..9)
    float v2 = 0.f, fs = 0.f;     // replicated

    for (int t = 0; t < T_; ++t) {
        // u[j] = x0[t-j] + x1[t-(63-j)], zero outside range (via padding)
        float u0 = px0[63 + t - lane] + px1[t + lane];          // j = lane
        float u1 = px0[31 + t - lane] + px1[t + lane + 32];     // j = lane+32

        // LIF: v += (u - v)/20, spike at >=1, hard reset
        vj0 = vj0 + __fdiv_rn(u0 - vj0, 20.0f);
        float s0 = (vj0 >= 1.0f) ? 1.0f : 0.0f;
        vj0 = (vj0 >= 1.0f) ? 0.0f : vj0;
        vj1 = vj1 + __fdiv_rn(u1 - vj1, 20.0f);
        float s1 = (vj1 >= 1.0f) ? 1.0f : 0.0f;
        vj1 = (vj1 >= 1.0f) ? 0.0f : vj1;

        // zc = sum_j s[j] * kint[j]  (butterfly -> all lanes hold result)
        float part = __fadd_rn(__fmul_rn(s0, k0), __fmul_rn(s1, k1));
        #pragma unroll
        for (int off = 16; off; off >>= 1)
            part += __shfl_xor_sync(0xffffffffu, part, off);

        // integrator IF
        vi = __fadd_rn(vi, part);
        float si = (vi >= 1.0f) ? 1.0f : 0.0f;
        vi = (vi >= 1.0f) ? 0.0f : vi;

        // f1 = f1 - f1/2 + si  (exact halving)
        f1 = f1 * 0.5f + si;

        // v1 = v1 + f1*w1 + b1 ; IF  (lanes 0..9, zeros elsewhere)
        v1 = __fadd_rn(__fadd_rn(v1, __fmul_rn(f1, w1k)), b1k);
        float sq = (v1 >= 1.0f) ? 1.0f : 0.0f;
        v1 = (v1 >= 1.0f) ? 0.0f : v1;

        f2 = f2 * 0.5f + sq;

        // v2 = v2 + dot(f2, w2) + b2 ; IF
        float p = __fmul_rn(f2, w2k);
        #pragma unroll
        for (int off = 16; off; off >>= 1)
            p += __shfl_xor_sync(0xffffffffu, p, off);
        v2 = __fadd_rn(__fadd_rn(v2, p), b2v);
        float s2 = (v2 >= 1.0f) ? 1.0f : 0.0f;
        v2 = (v2 >= 1.0f) ? 0.0f : v2;

        fs = fs * 0.5f + s2;
        if (lane == 0) g_fs[(t * N_ + n) * C_ + c] = fs;
    }
}

// ---------------------------------------------------------------------------
// K2: deterministic reduction over C: fssum[t][n] = sum_c fs[t][n][c]
// ---------------------------------------------------------------------------
__global__ __launch_bounds__(256) void k2_sumc()
{
    const int id   = blockIdx.x * 8 + (threadIdx.x >> 5);   // 0..2047 = t*N + n
    const int lane = threadIdx.x & 31;
    const float* __restrict__ p = g_fs + id * C_;
    float a = __fadd_rn(__fadd_rn(__fadd_rn(p[lane], p[lane + 32]), p[lane + 64]), p[lane + 96]);
    #pragma unroll
    for (int off = 16; off; off >>= 1)
        a += __shfl_xor_sync(0xffffffffu, a, off);
    if (lane == 0) g_fssum[id] = a;
}

// ---------------------------------------------------------------------------
// K3: one warp per n. sum-IF + sqrt model (32-wide layers), lane = unit index.
// ---------------------------------------------------------------------------
__global__ __launch_bounds__(32) void k3_sqrt(
    const float* __restrict__ sw0, const float* __restrict__ sb0,
    const float* __restrict__ sw1, const float* __restrict__ sb1,
    const float* __restrict__ sw2, const float* __restrict__ sb2,
    float* __restrict__ out)
{
    const int n    = blockIdx.x;
    const int lane = threadIdx.x;

    float r[32];                              // row `lane` of sw1
    #pragma unroll
    for (int j = 0; j < 32; ++j) r[j] = sw1[lane * 32 + j];
    const float sw0l = sw0[lane], sb0l = sb0[lane];
    const float sb1l = sb1[lane], sw2l = sw2[lane];
    const float sb2v = sb2[0];

    float vs = 0.f, g0 = 0.f, q0 = 0.f, g1 = 0.f, q1 = 0.f, g2 = 0.f, q2 = 0.f;

    for (int t = 0; t < T_; ++t) {
        float S = g_fssum[t * N_ + n];        // broadcast load

        // sum IF
        vs = __fadd_rn(vs, S);
        float h = (vs >= 1.0f) ? 1.0f : 0.0f;
        vs = (vs >= 1.0f) ? 0.0f : vs;

        g0 = g0 * 0.5f + h;
        q0 = __fadd_rn(__fadd_rn(q0, __fmul_rn(h, sw0l)), sb0l);
        float s0 = (q0 >= 1.0f) ? 1.0f : 0.0f;
        q0 = (q0 >= 1.0f) ? 0.0f : q0;

        g1 = g1 * 0.5f + s0;

        // q1 += g1 @ sw1.T (row dot via shuffles, 4-way split accumulators)
        float a0 = 0.f, a1 = 0.f, a2 = 0.f, a3 = 0.f;
        #pragma unroll
        for (int j = 0; j < 32; j += 4) {
            a0 = __fadd_rn(a0, __fmul_rn(__shfl_sync(0xffffffffu, g1, j),     r[j]));
            a1 = __fadd_rn(a1, __fmul_rn(__shfl_sync(0xffffffffu, g1, j + 1), r[j + 1]));
            a2 = __fadd_rn(a2, __fmul_rn(__shfl_sync(0xffffffffu, g1, j + 2), r[j + 2]));
            a3 = __fadd_rn(a3, __fmul_rn(__shfl_sync(0xffffffffu, g1, j + 3), r[j + 3]));
        }
        float dotv = __fadd_rn(__fadd_rn(a0, a1), __fadd_rn(a2, a3));
        q1 = __fadd_rn(__fadd_rn(q1, dotv), sb1l);
        float s1 = (q1 >= 1.0f) ? 1.0f : 0.0f;
        q1 = (q1 >= 1.0f) ? 0.0f : q1;

        g2 = g2 * 0.5f + s1;

        // q2 += dot(g2, sw2) + sb2 (NonSpikingIF: output = membrane)
        float p = __fmul_rn(g2, sw2l);
        #pragma unroll
        for (int off = 16; off; off >>= 1)
            p += __shfl_xor_sync(0xffffffffu, p, off);
        q2 = __fadd_rn(__fadd_rn(q2, p), sb2v);
        if (lane == 0) out[t * N_ + n] = q2;
    }
}

// ---------------------------------------------------------------------------
extern "C" void kernel_launch(void* const* d_in, const int* in_sizes, int n_in,
                              void* d_out, int out_size)
{
    const float* x   = (const float*)d_in[0];
    const float* w1  = (const float*)d_in[1];
    const float* b1  = (const float*)d_in[2];
    const float* w2  = (const float*)d_in[3];
    const float* b2  = (const float*)d_in[4];
    const float* sw0 = (const float*)d_in[5];
    const float* sb0 = (const float*)d_in[6];
    const float* sw1 = (const float*)d_in[7];
    const float* sb1 = (const float*)d_in[8];
    const float* sw2 = (const float*)d_in[9];
    const float* sb2 = (const float*)d_in[10];
    float* out = (float*)d_out;

    k1_chains<<<(N_ * C_) / 4, 128>>>(x, w1, b1, w2, b2);   // 1024 blocks x 4 warps
    k2_sumc<<<(T_ * N_) / 8, 256>>>();                      // 256 blocks
    k3_sqrt<<<N_, 32>>>(sw0, sb0, sw1, sb1, sw2, sb2, out); // 32 warps
}

// round 2
// speedup vs baseline: 1.9498x; 1.9498x over previous
#include <cuda_runtime.h>
#include <cuda_bf16.h>
#include <math.h>

#define T_  64
#define N_  32
#define C_  128
#define D_  64

// Scratch (no allocation allowed in kernel_launch)
__device__ float g_fs[T_ * N_ * C_];     // fs[t][n][c]

// Correctly-rounded d/20 via Markstein tail: 0.05f == rn(1/20), so the
// refined-quotient step yields rn(d/20) — bit-identical to fdiv.rn.f32,
// but 3 instructions with no FCHK/special-case branch.
__device__ __forceinline__ float div20_rn(float d) {
    float q = __fmul_rn(d, 0.05f);
    float r = __fmaf_rn(-20.0f, q, d);
    return __fmaf_rn(r, 0.05f, q);
}

// ---------------------------------------------------------------------------
// K1: one warp per (n,c) chain. Lane L owns Jeffress units j=L and j=L+32.
// Covers: Jeffress LIF -> kint dot -> integrator IF -> square model -> fs.
// ---------------------------------------------------------------------------
__global__ __launch_bounds__(128) void k1_chains(
    const float* __restrict__ x,
    const float* __restrict__ w1, const float* __restrict__ b1,
    const float* __restrict__ w2, const float* __restrict__ b2)
{
    __shared__ float xs0[4][128];   // x0 padded: xs0[w][63+t] = x0[t], [0..62]=0
    __shared__ float xs1[4][128];   // x1 padded likewise

    const int tid  = threadIdx.x;
    const int warp = tid >> 5;
    const int lane = tid & 31;
    const int chain  = blockIdx.x * 4 + warp;
    const int n      = chain >> 7;          // chain / C_
    const int c      = chain & 127;
    const int c_base = (blockIdx.x * 4) & 127;   // block spans 4 consecutive c, same n

    // Zero both smem arrays
    #pragma unroll
    for (int e = tid; e < 512; e += 128) {
        ((float*)xs0)[e] = 0.f;
        ((float*)xs1)[e] = 0.f;
    }
    __syncthreads();

    // Fill via one float4 load per thread: thread e -> (t = e>>1, i = e&1)
    {
        int t = tid >> 1;
        int i = tid & 1;
        const float4 v = *(const float4*)&x[((t * N_ + n) * 2 + i) * C_ + c_base];
        if (i == 0) {
            xs0[0][63 + t] = v.x; xs0[1][63 + t] = v.y;
            xs0[2][63 + t] = v.z; xs0[3][63 + t] = v.w;
        } else {
            xs1[0][63 + t] = v.x; xs1[1][63 + t] = v.y;
            xs1[2][63 + t] = v.z; xs1[3][63 + t] = v.w;
        }
    }
    __syncthreads();

    // kint for this lane's two units, computed in double (robust; the
    // |d|=32 weight sits 1 ulp above 1.0 and must not collapse).
    const int ad0 = 32 - lane;                       // j=lane    -> |d| in [1,32]
    const int ad1 = (lane == 0) ? 1 : lane;          // j=lane+32 -> |d|, d==0 clamped to 1
    const float k0 = (float)(1.0 / (1.0 - exp(-(double)ad0 * 0.5)));
    const float k1 = (float)(1.0 / (1.0 - exp(-(double)ad1 * 0.5)));

    // square-model params: lanes 0..9 active, others carry zeros (branchless)
    const float w1k = (lane < 10) ? w1[lane] : 0.f;
    const float b1k = (lane < 10) ? b1[lane] : 0.f;
    const float w2k = (lane < 10) ? w2[lane] : 0.f;
    const float b2v = b2[0];

    // p0[t] = xs0[warp][63 + t - lane], p1[t] = xs1[warp][t + lane]
    const float* __restrict__ p0 = &xs0[warp][63 - lane];
    const float* __restrict__ p1 = &xs1[warp][lane];

    float vj0 = 0.f, vj1 = 0.f;   // Jeffress LIF membranes (2 per lane)
    float vi = 0.f;               // integrator IF (replicated across lanes)
    float f1 = 0.f;               // filter 1 (replicated)
    float v1 = 0.f, f2 = 0.f;     // per-lane (lanes 0..9)
    float v2 = 0.f, fs = 0.f;     // replicated

    float* __restrict__ outp = g_fs + n * C_ + c;

    #pragma unroll 4
    for (int t = 0; t < T_; ++t) {
        // u[j] = x0[t-j] + x1[t-(63-j)], zero outside range (via padding)
        float u0 = p0[t] + p1[t];                 // j = lane
        float u1 = p0[t - 32] + p1[t + 32];       // j = lane+32

        // LIF: v += (u - v)/20, spike at >=1, hard reset
        vj0 = __fadd_rn(vj0, div20_rn(__fadd_rn(u0, -vj0)));
        float s0 = (vj0 >= 1.0f) ? 1.0f : 0.0f;
        vj0 = (vj0 >= 1.0f) ? 0.0f : vj0;
        vj1 = __fadd_rn(vj1, div20_rn(__fadd_rn(u1, -vj1)));
        float s1 = (vj1 >= 1.0f) ? 1.0f : 0.0f;
        vj1 = (vj1 >= 1.0f) ? 0.0f : vj1;

        // zc = sum_j s[j] * kint[j]  (5-level butterfly -> all lanes)
        float part = __fadd_rn(__fmul_rn(s0, k0), __fmul_rn(s1, k1));
        #pragma unroll
        for (int off = 16; off; off >>= 1)
            part += __shfl_xor_sync(0xffffffffu, part, off);

        // integrator IF
        vi = __fadd_rn(vi, part);
        float si = (vi >= 1.0f) ? 1.0f : 0.0f;
        vi = (vi >= 1.0f) ? 0.0f : vi;

        // f1 = f1 - f1/2 + si  (exact halving)
        f1 = f1 * 0.5f + si;

        // v1 = v1 + f1*w1 + b1 ; IF  (lanes 0..9, zeros elsewhere)
        v1 = __fadd_rn(__fadd_rn(v1, __fmul_rn(f1, w1k)), b1k);
        float sq = (v1 >= 1.0f) ? 1.0f : 0.0f;
        v1 = (v1 >= 1.0f) ? 0.0f : v1;

        f2 = f2 * 0.5f + sq;

        // v2 = v2 + dot(f2, w2) + b2 ; IF
        // Lanes 16..31 carry exact zeros, so the off=16 butterfly level adds
        // +0.0 and can be dropped bit-identically: 4-level reduce over 16.
        float p = __fmul_rn(f2, w2k);
        #pragma unroll
        for (int off = 8; off; off >>= 1)
            p += __shfl_xor_sync(0xffffffffu, p, off);
        v2 = __fadd_rn(__fadd_rn(v2, p), b2v);
        float s2 = (v2 >= 1.0f) ? 1.0f : 0.0f;
        v2 = (v2 >= 1.0f) ? 0.0f : v2;

        fs = fs * 0.5f + s2;
        if (lane == 0) outp[t * (N_ * C_)] = fs;
    }
}

// ---------------------------------------------------------------------------
// K3 (fused): block n. Phase 1: 4 warps reduce fs over C into SMEM (same
// rounding as the old k2). Phase 2: warp 0 runs the per-n recurrence with
// SMEM loads (29 cyc) instead of L2 LDG (~250 cyc) on the serial path.
// ---------------------------------------------------------------------------
__global__ __launch_bounds__(128) void k3_sqrt(
    const float* __restrict__ sw0, const float* __restrict__ sb0,
    const float* __restrict__ sw1, const float* __restrict__ sb1,
    const float* __restrict__ sw2, const float* __restrict__ sb2,
    float* __restrict__ out)
{
    __shared__ float Ssum[T_];

    const int n    = blockIdx.x;
    const int warp = threadIdx.x >> 5;
    const int lane = threadIdx.x & 31;

    // Phase 1: fssum[t] = sum_c fs[t][n][c], bit-identical to old k2:
    // lane partial ((p[l]+p[l+32])+p[l+64])+p[l+96], then 5-level butterfly.
    #pragma unroll
    for (int t = warp; t < T_; t += 4) {
        const float* __restrict__ p = g_fs + (t * N_ + n) * C_;
        float a = __fadd_rn(__fadd_rn(__fadd_rn(p[lane], p[lane + 32]), p[lane + 64]), p[lane + 96]);
        #pragma unroll
        for (int off = 16; off; off >>= 1)
            a += __shfl_xor_sync(0xffffffffu, a, off);
        if (lane == 0) Ssum[t] = a;
    }
    __syncthreads();

    if (warp != 0) return;

    float r[32];                              // row `lane` of sw1
    #pragma unroll
    for (int j = 0; j < 32; ++j) r[j] = sw1[lane * 32 + j];
    const float sw0l = sw0[lane], sb0l = sb0[lane];
    const float sb1l = sb1[lane], sw2l = sw2[lane];
    const float sb2v = sb2[0];

    float vs = 0.f, g0 = 0.f, q0 = 0.f, g1 = 0.f, q1 = 0.f, g2 = 0.f, q2 = 0.f;

    #pragma unroll 4
    for (int t = 0; t < T_; ++t) {
        float S = Ssum[t];

        // sum IF
        vs = __fadd_rn(vs, S);
        float h = (vs >= 1.0f) ? 1.0f : 0.0f;
        vs = (vs >= 1.0f) ? 0.0f : vs;

        g0 = g0 * 0.5f + h;
        q0 = __fadd_rn(__fadd_rn(q0, __fmul_rn(h, sw0l)), sb0l);
        float s0 = (q0 >= 1.0f) ? 1.0f : 0.0f;
        q0 = (q0 >= 1.0f) ? 0.0f : q0;

        g1 = g1 * 0.5f + s0;

        // q1 += g1 @ sw1.T (row dot via shuffles, 4-way split accumulators)
        float a0 = 0.f, a1 = 0.f, a2 = 0.f, a3 = 0.f;
        #pragma unroll
        for (int j = 0; j < 32; j += 4) {
            a0 = __fadd_rn(a0, __fmul_rn(__shfl_sync(0xffffffffu, g1, j),     r[j]));
            a1 = __fadd_rn(a1, __fmul_rn(__shfl_sync(0xffffffffu, g1, j + 1), r[j + 1]));
            a2 = __fadd_rn(a2, __fmul_rn(__shfl_sync(0xffffffffu, g1, j + 2), r[j + 2]));
            a3 = __fadd_rn(a3, __fmul_rn(__shfl_sync(0xffffffffu, g1, j + 3), r[j + 3]));
        }
        float dotv = __fadd_rn(__fadd_rn(a0, a1), __fadd_rn(a2, a3));
        q1 = __fadd_rn(__fadd_rn(q1, dotv), sb1l);
        float s1 = (q1 >= 1.0f) ? 1.0f : 0.0f;
        q1 = (q1 >= 1.0f) ? 0.0f : q1;

        g2 = g2 * 0.5f + s1;

        // q2 += dot(g2, sw2) + sb2 (NonSpikingIF: output = membrane).
        // Off the recurrence critical path — feeds only the output.
        float p = __fmul_rn(g2, sw2l);
        #pragma unroll
        for (int off = 16; off; off >>= 1)
            p += __shfl_xor_sync(0xffffffffu, p, off);
        q2 = __fadd_rn(__fadd_rn(q2, p), sb2v);
        if (lane == 0) out[t * N_ + n] = q2;
    }
}

// ---------------------------------------------------------------------------
extern "C" void kernel_launch(void* const* d_in, const int* in_sizes, int n_in,
                              void* d_out, int out_size)
{
    const float* x   = (const float*)d_in[0];
    const float* w1  = (const float*)d_in[1];
    const float* b1  = (const float*)d_in[2];
    const float* w2  = (const float*)d_in[3];
    const float* b2  = (const float*)d_in[4];
    const float* sw0 = (const float*)d_in[5];
    const float* sb0 = (const float*)d_in[6];
    const float* sw1 = (const float*)d_in[7];
    const float* sb1 = (const float*)d_in[8];
    const float* sw2 = (const float*)d_in[9];
    const float* sb2 = (const float*)d_in[10];
    float* out = (float*)d_out;

    k1_chains<<<(N_ * C_) / 4, 128>>>(x, w1, b1, w2, b2);   // 1024 blocks x 4 warps
    k3_sqrt<<<N_, 128>>>(sw0, sb0, sw1, sb1, sw2, sb2, out); // 32 blocks
}